// round 1
// baseline (speedup 1.0000x reference)
#include <cuda_runtime.h>
#include <cuda_bf16.h>
#include <math.h>

// Problem constants
#define B_   4
#define C_   128
#define H_   64
#define W_   64
#define OUT_ 128
#define LK   25          // L*L
#define NPIX (B_*H_*W_)  // 16384

// Device scratch (no dynamic allocation allowed)
__device__ float g_w1r[C_ * 9 * 32];      // [c][tap][k padded to 32]
__device__ float g_w2t[C_ * OUT_];        // [c][o]  (w2eff transposed)
__device__ float g_softk[NPIX * 32];      // [pix][k padded to 32]

// ---------------------------------------------------------------------------
// Kernel 0: weight preprocessing
//   w1  [25,128,3,3] -> g_w1r[(c*9+t)*32 + k]
//   w2  [128, 512]   -> g_w2t[c*128 + o] = sum_r w2[o, 4c+r]
// ---------------------------------------------------------------------------
__global__ void prep_kernel(const float* __restrict__ w1,
                            const float* __restrict__ w2) {
    int i = blockIdx.x * blockDim.x + threadIdx.x;
    if (i < C_ * 9 * 32) {
        int k  = i & 31;
        int ct = i >> 5;
        int c  = ct / 9;
        int t  = ct - c * 9;
        float v = 0.f;
        if (k < LK) {
            int ty = t / 3, tx = t - ty * 3;
            v = w1[((k * C_ + c) * 3 + ty) * 3 + tx];
        }
        g_w1r[i] = v;
    }
    if (i < C_ * OUT_) {
        int o = i & 127;
        int c = i >> 7;
        const float* p = w2 + o * (4 * C_) + c * 4;
        g_w2t[i] = p[0] + p[1] + p[2] + p[3];
    }
}

// ---------------------------------------------------------------------------
// Kernel 1: conv1 (3x3 SAME, 128->25) + bias + softmax over 25
// Grid: 256 blocks (one per 8x8 pixel tile), 128 threads.
// Thread layout: cg = tid>>5 (channel group of 32), pt = tid&31.
// Each thread computes 2 pixels (pt and pt+32) so weight LDGs amortize.
// smem: x tile 128ch x 10x10 (row stride 12) + partial buffer.
// ---------------------------------------------------------------------------
#define K1_XS   (C_ * 120)        // 15360 floats
#define K1_RED  (64 * 4 * 26)     // 6656 floats
#define K1_SMEM ((K1_XS + K1_RED) * 4)

__global__ void __launch_bounds__(128, 2)
conv_softmax_kernel(const float* __restrict__ x, const float* __restrict__ b1) {
    extern __shared__ float sm[];
    float* xs  = sm;
    float* red = sm + K1_XS;

    int tid = threadIdx.x;
    int blk = blockIdx.x;
    int b   = blk >> 6;
    int t   = blk & 63;
    int h0  = (t >> 3) * 8;
    int w0  = (t & 7) * 8;
    const float* xb = x + b * C_ * H_ * W_;

    // Load 10x10 halo tile for all 128 channels (zero-padded)
    for (int i = tid; i < C_ * 100; i += 128) {
        int c   = i / 100;
        int rem = i - c * 100;
        int yy  = rem / 10;
        int xx  = rem - yy * 10;
        int h = h0 - 1 + yy, w = w0 - 1 + xx;
        float v = 0.f;
        if ((unsigned)h < H_ && (unsigned)w < W_) v = xb[(c * H_ + h) * W_ + w];
        xs[c * 120 + yy * 12 + xx] = v;
    }
    __syncthreads();

    int cg  = tid >> 5;
    int pt  = tid & 31;
    int py  = pt >> 3;
    int pxx = pt & 7;

    float acc0[25], acc1[25];
#pragma unroll
    for (int k = 0; k < 25; k++) { acc0[k] = 0.f; acc1[k] = 0.f; }

    const float4* wr = (const float4*)g_w1r;
    for (int cc = 0; cc < 32; ++cc) {
        int c = cg * 32 + cc;
        const float* xc = xs + c * 120;
        float xv0[9], xv1[9];
#pragma unroll
        for (int dy = 0; dy < 3; dy++)
#pragma unroll
            for (int dx = 0; dx < 3; dx++) {
                xv0[dy * 3 + dx] = xc[(py + dy) * 12 + pxx + dx];
                xv1[dy * 3 + dx] = xc[(py + 4 + dy) * 12 + pxx + dx];
            }
#pragma unroll
        for (int t9 = 0; t9 < 9; t9++) {
            const float4* w4 = wr + (c * 9 + t9) * 8;
            float a0 = xv0[t9], a1 = xv1[t9];
#pragma unroll
            for (int kk = 0; kk < 6; kk++) {
                float4 wv = w4[kk];
                acc0[kk * 4 + 0] += a0 * wv.x;  acc1[kk * 4 + 0] += a1 * wv.x;
                acc0[kk * 4 + 1] += a0 * wv.y;  acc1[kk * 4 + 1] += a1 * wv.y;
                acc0[kk * 4 + 2] += a0 * wv.z;  acc1[kk * 4 + 2] += a1 * wv.z;
                acc0[kk * 4 + 3] += a0 * wv.w;  acc1[kk * 4 + 3] += a1 * wv.w;
            }
            float w24 = ((const float*)w4)[24];
            acc0[24] += a0 * w24;  acc1[24] += a1 * w24;
        }
    }

    // stash partials: red[(px*4+cg)*26 + k]
#pragma unroll
    for (int k = 0; k < 25; k++) {
        red[(pt * 4 + cg) * 26 + k]        = acc0[k];
        red[((pt + 32) * 4 + cg) * 26 + k] = acc1[k];
    }
    __syncthreads();

    // one thread per pixel: reduce 4 partials, add bias, softmax, write out
    if (tid < 64) {
        int px = tid;
        float s[25];
        float m = -1e30f;
#pragma unroll
        for (int k = 0; k < 25; k++) {
            float v = red[(px * 4 + 0) * 26 + k]
                    + red[(px * 4 + 1) * 26 + k]
                    + red[(px * 4 + 2) * 26 + k]
                    + red[(px * 4 + 3) * 26 + k]
                    + b1[k];
            s[k] = v;
            m = fmaxf(m, v);
        }
        float tot = 0.f;
#pragma unroll
        for (int k = 0; k < 25; k++) { s[k] = expf(s[k] - m); tot += s[k]; }
        float inv = 1.f / tot;
        int py2 = px >> 3, px2 = px & 7;
        int gpix = b * (H_ * W_) + (h0 + py2) * W_ + (w0 + px2);
        float* dst = g_softk + gpix * 32;
#pragma unroll
        for (int k = 0; k < 25; k++) dst[k] = s[k] * inv;
    }
}

// ---------------------------------------------------------------------------
// Kernel 2: 5x5 window combine (y) + 128x128 matvec (z) + x2 upsample write
// Grid: 256 blocks (8x8 pixel tile), 256 threads.
// smem: x tile 128 x 12x12  +  w2t 128x128  +  y staging [c][64]
// ---------------------------------------------------------------------------
#define K2_XS  (C_ * 144)     // 18432
#define K2_WS  (C_ * OUT_)    // 16384
#define K2_YS  (C_ * 64)      // 8192
#define K2_SMEM ((K2_XS + K2_WS + K2_YS) * 4)

__global__ void __launch_bounds__(256, 1)
assemble_kernel(const float* __restrict__ x, const float* __restrict__ b2,
                float* __restrict__ out) {
    extern __shared__ float sm[];
    float* xs = sm;
    float* ws = sm + K2_XS;
    float* ys = sm + K2_XS + K2_WS;

    int tid = threadIdx.x;
    int blk = blockIdx.x;
    int b   = blk >> 6;
    int t   = blk & 63;
    int h0  = (t >> 3) * 8;
    int w0  = (t & 7) * 8;
    const float* xb = x + b * C_ * H_ * W_;

    // Load 12x12 halo tile (pad 2, zero fill)
    for (int i = tid; i < C_ * 144; i += 256) {
        int c   = i / 144;
        int rem = i - c * 144;
        int yy  = rem / 12;
        int xx  = rem - yy * 12;
        int h = h0 - 2 + yy, w = w0 - 2 + xx;
        float v = 0.f;
        if ((unsigned)h < H_ && (unsigned)w < W_) v = xb[(c * H_ + h) * W_ + w];
        xs[i] = v;
    }
    // Load folded w2 transpose
    for (int i = tid; i < K2_WS; i += 256) ws[i] = g_w2t[i];
    __syncthreads();

    // ---- y phase: y[c][px] = sum_k softk[px][k] * window(c, px, k) ----
    {
        int cq  = tid >> 6;          // channel quarter (warps uniform in cq)
        int px  = tid & 63;
        int py  = px >> 3;
        int pxx = px & 7;
        int gpix = b * (H_ * W_) + (h0 + py) * W_ + (w0 + pxx);
        const float* skp = g_softk + gpix * 32;
        float s[25];
#pragma unroll
        for (int k = 0; k < 24; k += 4) {
            float4 v = *(const float4*)(skp + k);
            s[k] = v.x; s[k + 1] = v.y; s[k + 2] = v.z; s[k + 3] = v.w;
        }
        s[24] = skp[24];
        const float* xw = xs + py * 12 + pxx;
        for (int cc = 0; cc < 32; cc++) {
            int c = cq * 32 + cc;
            const float* xc = xw + c * 144;
            float acc = 0.f;
#pragma unroll
            for (int ky = 0; ky < 5; ky++)
#pragma unroll
                for (int kx = 0; kx < 5; kx++)
                    acc += s[ky * 5 + kx] * xc[ky * 12 + kx];
            ys[c * 64 + px] = acc;
        }
    }
    __syncthreads();

    // ---- z phase: z[o][px] = sum_c w2t[c][o] * y[c][px] + b2[o] ----
    {
        int w = tid >> 5;       // warp id -> pixel row group (8 px)
        int l = tid & 31;       // lane -> o = 4l..4l+3
        float acc[8][4];
#pragma unroll
        for (int pi = 0; pi < 8; pi++)
#pragma unroll
            for (int q = 0; q < 4; q++) acc[pi][q] = 0.f;

        const float* wsl = ws + 4 * l;
        const float* ysw = ys + w * 8;
        for (int c = 0; c < 128; c++) {
            float4 wv = *(const float4*)(wsl + c * 128);
            float4 y0 = *(const float4*)(ysw + c * 64);
            float4 y1 = *(const float4*)(ysw + c * 64 + 4);
            float yv[8] = {y0.x, y0.y, y0.z, y0.w, y1.x, y1.y, y1.z, y1.w};
#pragma unroll
            for (int pi = 0; pi < 8; pi++) {
                acc[pi][0] += yv[pi] * wv.x;
                acc[pi][1] += yv[pi] * wv.y;
                acc[pi][2] += yv[pi] * wv.z;
                acc[pi][3] += yv[pi] * wv.w;
            }
        }

        float4 bb = *(const float4*)(b2 + 4 * l);
        float bq[4] = {bb.x, bb.y, bb.z, bb.w};
        int hh = h0 + w;   // source pixel row
#pragma unroll
        for (int q = 0; q < 4; q++) {
            int o = 4 * l + q;
            float* ob = out + (((size_t)(b * OUT_ + o) * (2 * H_)) + 2 * hh) * (2 * W_) + 2 * w0;
#pragma unroll
            for (int pi = 0; pi < 8; pi += 2) {
                float z0 = acc[pi][q] + bq[q];
                float z1 = acc[pi + 1][q] + bq[q];
                float4 v = make_float4(z0, z0, z1, z1);
                *(float4*)(ob + 2 * pi)             = v;   // row 2h
                *(float4*)(ob + 2 * W_ + 2 * pi)    = v;   // row 2h+1
            }
        }
    }
}

// ---------------------------------------------------------------------------
extern "C" void kernel_launch(void* const* d_in, const int* in_sizes, int n_in,
                              void* d_out, int out_size) {
    const float* x  = (const float*)d_in[0];
    const float* w1 = (const float*)d_in[1];
    const float* b1 = (const float*)d_in[2];
    const float* w2 = (const float*)d_in[3];
    const float* b2 = (const float*)d_in[4];
    float* out = (float*)d_out;

    cudaFuncSetAttribute(conv_softmax_kernel,
                         cudaFuncAttributeMaxDynamicSharedMemorySize, K1_SMEM);
    cudaFuncSetAttribute(assemble_kernel,
                         cudaFuncAttributeMaxDynamicSharedMemorySize, K2_SMEM);

    prep_kernel<<<(C_ * 9 * 32 + 255) / 256, 256>>>(w1, w2);
    conv_softmax_kernel<<<256, 128, K1_SMEM>>>(x, b1);
    assemble_kernel<<<256, 256, K2_SMEM>>>(x, b2, out);
}

// round 2
// speedup vs baseline: 1.1316x; 1.1316x over previous
#include <cuda_runtime.h>
#include <cuda_bf16.h>
#include <math.h>

// Problem constants
#define B_   4
#define C_   128
#define H_   64
#define W_   64
#define OUT_ 128
#define LK   25

// Device scratch (no dynamic allocation allowed)
__device__ float g_w1r[C_ * 9 * 28];      // [c][tap][k padded to 28], k>=25 zero
__device__ float g_w2t[C_ * OUT_];        // [c][o]  (folded w2, transposed)

// ---------------------------------------------------------------------------
// Kernel 0: weight preprocessing (source-coalesced)
//   w1 [25,128,3,3] -> g_w1r[(c*9+t)*28 + k]   (k = 25..27 zero)
//   w2 [128,512]    -> g_w2t[c*128+o] = sum_r w2[o,4c+r]
// ---------------------------------------------------------------------------
__global__ void prep_kernel(const float* __restrict__ w1,
                            const float* __restrict__ w2) {
    int i = blockIdx.x * blockDim.x + threadIdx.x;
    // w1 reorder: i enumerates the SOURCE linearly -> coalesced reads
    if (i < LK * C_ * 9) {
        int k   = i / (C_ * 9);
        int rem = i - k * (C_ * 9);      // c*9 + t
        g_w1r[rem * 28 + k] = w1[i];
    }
    // zero the pad slots k = 25..27
    int j = i - LK * C_ * 9;
    if (j >= 0 && j < C_ * 9 * 3) {
        int ct = j / 3;
        int kk = 25 + (j - ct * 3);
        g_w1r[ct * 28 + kk] = 0.f;
    }
    // w2 fold: i enumerates (o, c) with c fastest -> coalesced float4 reads
    if (i < C_ * OUT_) {
        int o = i >> 7;
        int c = i & 127;
        float4 p = ((const float4*)w2)[i];
        g_w2t[c * 128 + o] = p.x + p.y + p.z + p.w;
    }
}

// ---------------------------------------------------------------------------
// Fused kernel: conv1(3x3)+softmax + 5x5 window combine + 128x128 matvec +
//               x2 nearest upsample write.
// Grid: 256 blocks (one 8x8 pixel tile each), 128 threads, 2 blocks/SM.
//
// smem (floats):
//   xs   [128][12][12]  18432   x tile, halo 2
//   ybuf                 8192   time-shared: wbuf(8064) -> red(6912) -> ys(8192)
//   sk   [26][64]        1664   softmax result, k-major
// total 28288 floats = 113152 B  -> 2 blocks/SM (226 KB)
// ---------------------------------------------------------------------------
#define SM_XS   (C_ * 144)          // 18432
#define SM_YB   8192
#define SM_SK   (26 * 64)           // 1664
#define SM_TOT  ((SM_XS + SM_YB + SM_SK) * 4)

__global__ void __launch_bounds__(128, 2)
fused_kernel(const float* __restrict__ x, const float* __restrict__ b1,
             const float* __restrict__ b2, float* __restrict__ out) {
    extern __shared__ float sm[];
    float* xs = sm;
    float* yb = sm + SM_XS;          // wbuf / red / ys
    float* sk = sm + SM_XS + SM_YB;  // softmax [k][px]

    int tid = threadIdx.x;
    int blk = blockIdx.x;
    int b   = blk >> 6;
    int t   = blk & 63;
    int h0  = (t >> 3) * 8;
    int w0  = (t & 7) * 8;
    const float* xb = x + b * C_ * H_ * W_;

    // ---- load 12x12 halo-2 tile for all 128 channels (zero pad) ----
    for (int i = tid; i < C_ * 144; i += 128) {
        int c   = i / 144;
        int rem = i - c * 144;
        int yy  = rem / 12;
        int xx  = rem - yy * 12;
        int h = h0 - 2 + yy, w = w0 - 2 + xx;
        float v = 0.f;
        if ((unsigned)h < H_ && (unsigned)w < W_) v = xb[(c * H_ + h) * W_ + w];
        xs[i] = v;
    }

    // ---- conv1 phase: cg = warp (channel residue mod 4), 2 px per thread ----
    int cg  = tid >> 5;
    int pt  = tid & 31;
    int py  = pt >> 3;
    int pxx = pt & 7;

    float acc0[25], acc1[25];
#pragma unroll
    for (int k = 0; k < 25; k++) { acc0[k] = 0.f; acc1[k] = 0.f; }

    for (int j = 0; j < 4; j++) {
        __syncthreads();                       // xs ready (j=0) / wbuf free
        const float* src = g_w1r + j * (32 * 9 * 28);
        for (int i = tid; i < 32 * 9 * 28; i += 128) yb[i] = src[i];
        __syncthreads();

#pragma unroll 2
        for (int cc = 0; cc < 8; cc++) {
            int cl = cc * 4 + cg;              // local channel in chunk
            int c  = j * 32 + cl;              // global channel
            const float* xc = xs + c * 144;
            float xv0[9], xv1[9];
#pragma unroll
            for (int dy = 0; dy < 3; dy++)
#pragma unroll
                for (int dx = 0; dx < 3; dx++) {
                    xv0[dy * 3 + dx] = xc[(py + 1 + dy) * 12 + pxx + 1 + dx];
                    xv1[dy * 3 + dx] = xc[(py + 5 + dy) * 12 + pxx + 1 + dx];
                }
            const float* wp = yb + cl * (9 * 28);
#pragma unroll
            for (int t9 = 0; t9 < 9; t9++) {
                const float4* w4 = (const float4*)(wp + t9 * 28);
                float a0 = xv0[t9], a1 = xv1[t9];
#pragma unroll
                for (int kk = 0; kk < 6; kk++) {
                    float4 wv = w4[kk];
                    acc0[kk * 4 + 0] += a0 * wv.x;  acc1[kk * 4 + 0] += a1 * wv.x;
                    acc0[kk * 4 + 1] += a0 * wv.y;  acc1[kk * 4 + 1] += a1 * wv.y;
                    acc0[kk * 4 + 2] += a0 * wv.z;  acc1[kk * 4 + 2] += a1 * wv.z;
                    acc0[kk * 4 + 3] += a0 * wv.w;  acc1[kk * 4 + 3] += a1 * wv.w;
                }
                float w24 = wp[t9 * 28 + 24];
                acc0[24] += a0 * w24;  acc1[24] += a1 * w24;
            }
        }
    }

    __syncthreads();                           // all chunks consumed
    // stash partials into red: yb[(cg*64+px)*27 + k]  (stride 27: conflict-free)
#pragma unroll
    for (int k = 0; k < 25; k++) {
        yb[(cg * 64 + pt) * 27 + k]      = acc0[k];
        yb[(cg * 64 + pt + 32) * 27 + k] = acc1[k];
    }
    __syncthreads();

    // ---- softmax: one thread per pixel ----
    if (tid < 64) {
        int px = tid;
        float s[25];
        float m = -1e30f;
#pragma unroll
        for (int k = 0; k < 25; k++) {
            float v = yb[(0 * 64 + px) * 27 + k]
                    + yb[(1 * 64 + px) * 27 + k]
                    + yb[(2 * 64 + px) * 27 + k]
                    + yb[(3 * 64 + px) * 27 + k]
                    + b1[k];
            s[k] = v;
            m = fmaxf(m, v);
        }
        float tot = 0.f;
#pragma unroll
        for (int k = 0; k < 25; k++) { s[k] = __expf(s[k] - m); tot += s[k]; }
        float inv = 1.f / tot;
#pragma unroll
        for (int k = 0; k < 25; k++) sk[k * 64 + px] = s[k] * inv;
    }
    __syncthreads();

    // ---- y phase: y[c][px] = sum_k s[px][k] * x[c, px+win(k)] ----
    {
        int cq  = tid >> 6;                   // channel half
        int px  = tid & 63;
        int py2 = px >> 3;
        int px2 = px & 7;
        float s[25];
#pragma unroll
        for (int k = 0; k < 25; k++) s[k] = sk[k * 64 + px];
        const float* xw = xs + py2 * 12 + px2;
#pragma unroll 2
        for (int cc = 0; cc < 64; cc++) {
            int c = cq * 64 + cc;
            const float* xc = xw + c * 144;
            float acc = 0.f;
#pragma unroll
            for (int ky = 0; ky < 5; ky++)
#pragma unroll
                for (int kx = 0; kx < 5; kx++)
                    acc += s[ky * 5 + kx] * xc[ky * 12 + kx];
            yb[c * 64 + px] = acc;            // ys (red fully consumed)
        }
    }
    __syncthreads();

    // ---- z phase: z[o][px] = sum_c w2t[c][o] * y[c][px] + b2[o] ----
    {
        int w = tid >> 5;                     // warp -> 16 px (2 source rows)
        int l = tid & 31;                     // lane -> o = 4l..4l+3
        float acc[16][4];
#pragma unroll
        for (int pi = 0; pi < 16; pi++)
#pragma unroll
            for (int q = 0; q < 4; q++) acc[pi][q] = 0.f;

        const float* wsl = g_w2t + 4 * l;
        const float* ysw = yb + w * 16;
#pragma unroll 2
        for (int c = 0; c < 128; c++) {
            float4 wv = *(const float4*)(wsl + c * 128);   // coalesced L2
            float4 y0 = *(const float4*)(ysw + c * 64);
            float4 y1 = *(const float4*)(ysw + c * 64 + 4);
            float4 y2 = *(const float4*)(ysw + c * 64 + 8);
            float4 y3 = *(const float4*)(ysw + c * 64 + 12);
            float yv[16] = {y0.x, y0.y, y0.z, y0.w, y1.x, y1.y, y1.z, y1.w,
                            y2.x, y2.y, y2.z, y2.w, y3.x, y3.y, y3.z, y3.w};
#pragma unroll
            for (int pi = 0; pi < 16; pi++) {
                acc[pi][0] += yv[pi] * wv.x;
                acc[pi][1] += yv[pi] * wv.y;
                acc[pi][2] += yv[pi] * wv.z;
                acc[pi][3] += yv[pi] * wv.w;
            }
        }

        float4 bb = *(const float4*)(b2 + 4 * l);
        float bq[4] = {bb.x, bb.y, bb.z, bb.w};
#pragma unroll
        for (int q = 0; q < 4; q++) {
            int o = 4 * l + q;
#pragma unroll
            for (int rr = 0; rr < 2; rr++) {
                int hh = h0 + 2 * w + rr;     // source row
                float* rowp = out + (((size_t)(b * OUT_ + o) * (2 * H_)) + 2 * hh) * (2 * W_) + 2 * w0;
#pragma unroll
                for (int pr = 0; pr < 4; pr++) {
                    float z0 = acc[rr * 8 + 2 * pr][q] + bq[q];
                    float z1 = acc[rr * 8 + 2 * pr + 1][q] + bq[q];
                    float4 v = make_float4(z0, z0, z1, z1);
                    *(float4*)(rowp + 4 * pr)            = v;   // row 2h
                    *(float4*)(rowp + 2 * W_ + 4 * pr)   = v;   // row 2h+1
                }
            }
        }
    }
}

// ---------------------------------------------------------------------------
extern "C" void kernel_launch(void* const* d_in, const int* in_sizes, int n_in,
                              void* d_out, int out_size) {
    const float* x  = (const float*)d_in[0];
    const float* w1 = (const float*)d_in[1];
    const float* b1 = (const float*)d_in[2];
    const float* w2 = (const float*)d_in[3];
    const float* b2 = (const float*)d_in[4];
    float* out = (float*)d_out;

    cudaFuncSetAttribute(fused_kernel,
                         cudaFuncAttributeMaxDynamicSharedMemorySize, SM_TOT);

    prep_kernel<<<(LK * C_ * 9 + C_ * 9 * 3 + 255) / 256, 256>>>(w1, w2);
    fused_kernel<<<256, 128, SM_TOT>>>(x, b1, b2, out);
}

// round 3
// speedup vs baseline: 1.1767x; 1.0399x over previous
#include <cuda_runtime.h>
#include <cuda_bf16.h>
#include <math.h>

// Problem constants
#define B_   4
#define C_   128
#define H_   64
#define W_   64
#define OUT_ 128
#define LK   25

// Device scratch (no dynamic allocation allowed)
__device__ float g_w1r[C_ * 9 * 28];      // [c][tap][k padded to 28], k>=25 zero
__device__ float g_w2t[C_ * OUT_];        // [c][o]  (folded w2, transposed)

// ---------------------------------------------------------------------------
// Kernel 0: weight preprocessing (source-coalesced)
// ---------------------------------------------------------------------------
__global__ void prep_kernel(const float* __restrict__ w1,
                            const float* __restrict__ w2) {
    int i = blockIdx.x * blockDim.x + threadIdx.x;
    if (i < LK * C_ * 9) {
        int k   = i / (C_ * 9);
        int rem = i - k * (C_ * 9);      // c*9 + t
        g_w1r[rem * 28 + k] = w1[i];
    }
    int j = i - LK * C_ * 9;
    if (j >= 0 && j < C_ * 9 * 3) {
        int ct = j / 3;
        int kk = 25 + (j - ct * 3);
        g_w1r[ct * 28 + kk] = 0.f;
    }
    if (i < C_ * OUT_) {
        int o = i >> 7;
        int c = i & 127;
        float4 p = ((const float4*)w2)[i];
        g_w2t[c * 128 + o] = p.x + p.y + p.z + p.w;
    }
}

// ---------------------------------------------------------------------------
// Fused kernel, 256 threads / block, 2 blocks/SM (16 warps/SM).
// smem (floats):
//   xs [128][12][12] 18432 | yb 8192 (wbuf->red->ys) | sk [26][64] 1664
// total 28288 floats = 113152 B
// ---------------------------------------------------------------------------
#define SM_XS   (C_ * 144)
#define SM_YB   8192
#define SM_SK   (26 * 64)
#define SM_TOT  ((SM_XS + SM_YB + SM_SK) * 4)

__global__ void __launch_bounds__(256, 2)
fused_kernel(const float* __restrict__ x, const float* __restrict__ b1,
             const float* __restrict__ b2, float* __restrict__ out) {
    extern __shared__ float sm[];
    float* xs = sm;
    float* yb = sm + SM_XS;          // wbuf / red / ys (time-shared)
    float* sk = sm + SM_XS + SM_YB;  // softmax [k][px]

    int tid = threadIdx.x;
    int blk = blockIdx.x;
    int b   = blk >> 6;
    int t   = blk & 63;
    int h0  = (t >> 3) * 8;
    int w0  = (t & 7) * 8;
    const float* xb = x + b * C_ * H_ * W_;

    // ---- load 12x12 halo-2 tile for all 128 channels (zero pad) ----
    for (int i = tid; i < C_ * 144; i += 256) {
        int c   = i / 144;
        int rem = i - c * 144;
        int yy  = rem / 12;
        int xx  = rem - yy * 12;
        int h = h0 - 2 + yy, w = w0 - 2 + xx;
        float v = 0.f;
        if ((unsigned)h < H_ && (unsigned)w < W_) v = xb[(c * H_ + h) * W_ + w];
        xs[i] = v;
    }

    // ---- conv1: cg = channel group (tid>>6), one pixel per thread ----
    int cg  = tid >> 6;              // 0..3
    int px  = tid & 63;
    int py  = px >> 3;
    int pxx = px & 7;

    float acc[25];
#pragma unroll
    for (int k = 0; k < 25; k++) acc[k] = 0.f;

    for (int j = 0; j < 4; j++) {
        __syncthreads();                       // xs ready (j=0) / wbuf free
        const float* src = g_w1r + j * (32 * 9 * 28);
        for (int i = tid; i < 32 * 9 * 28; i += 256) yb[i] = src[i];
        __syncthreads();

#pragma unroll 2
        for (int cc = 0; cc < 8; cc++) {
            int cl = cc * 4 + cg;              // local channel in chunk
            int c  = j * 32 + cl;              // global channel
            const float* xc = xs + c * 144;
            float xv[9];
#pragma unroll
            for (int dy = 0; dy < 3; dy++)
#pragma unroll
                for (int dx = 0; dx < 3; dx++)
                    xv[dy * 3 + dx] = xc[(py + 1 + dy) * 12 + pxx + 1 + dx];
            const float* wp = yb + cl * (9 * 28);
#pragma unroll
            for (int t9 = 0; t9 < 9; t9++) {
                const float4* w4 = (const float4*)(wp + t9 * 28);
                float a0 = xv[t9];
#pragma unroll
                for (int kk = 0; kk < 6; kk++) {
                    float4 wv = w4[kk];
                    acc[kk * 4 + 0] += a0 * wv.x;
                    acc[kk * 4 + 1] += a0 * wv.y;
                    acc[kk * 4 + 2] += a0 * wv.z;
                    acc[kk * 4 + 3] += a0 * wv.w;
                }
                acc[24] += a0 * wp[t9 * 28 + 24];
            }
        }
    }

    __syncthreads();
    // stash partials: red[(cg*64+px)*27 + k]  (stride 27: conflict-free)
#pragma unroll
    for (int k = 0; k < 25; k++)
        yb[(cg * 64 + px) * 27 + k] = acc[k];
    __syncthreads();

    // ---- softmax: one thread per pixel ----
    if (tid < 64) {
        int p = tid;
        float s[25];
        float m = -1e30f;
#pragma unroll
        for (int k = 0; k < 25; k++) {
            float v = yb[(0 * 64 + p) * 27 + k]
                    + yb[(1 * 64 + p) * 27 + k]
                    + yb[(2 * 64 + p) * 27 + k]
                    + yb[(3 * 64 + p) * 27 + k]
                    + b1[k];
            s[k] = v;
            m = fmaxf(m, v);
        }
        float tot = 0.f;
#pragma unroll
        for (int k = 0; k < 25; k++) { s[k] = __expf(s[k] - m); tot += s[k]; }
        float inv = 1.f / tot;
#pragma unroll
        for (int k = 0; k < 25; k++) sk[k * 64 + p] = s[k] * inv;
    }
    __syncthreads();

    // ---- y phase: y[c][px] = sum_k s[px][k] * x[c, px+win(k)] ----
    {
        int cq  = tid >> 6;                   // channel quarter
        float s[25];
#pragma unroll
        for (int k = 0; k < 25; k++) s[k] = sk[k * 64 + px];
        const float* xw = xs + py * 12 + pxx;
#pragma unroll 2
        for (int cc = 0; cc < 32; cc++) {
            int c = cq * 32 + cc;
            const float* xc = xw + c * 144;
            float a = 0.f;
#pragma unroll
            for (int ky = 0; ky < 5; ky++)
#pragma unroll
                for (int kx = 0; kx < 5; kx++)
                    a += s[ky * 5 + kx] * xc[ky * 12 + kx];
            yb[c * 64 + px] = a;              // ys (red fully consumed)
        }
    }
    __syncthreads();

    // ---- z phase: z[o][px] = sum_c w2t[c][o] * y[c][px] + b2[o] ----
    {
        int w = tid >> 5;                     // warp -> 8 px (one source row)
        int l = tid & 31;                     // lane -> o = 4l..4l+3
        float za[8][4];
#pragma unroll
        for (int pi = 0; pi < 8; pi++)
#pragma unroll
            for (int q = 0; q < 4; q++) za[pi][q] = 0.f;

        const float* wsl = g_w2t + 4 * l;
        const float* ysw = yb + w * 8;
#pragma unroll 4
        for (int c = 0; c < 128; c++) {
            float4 wv = *(const float4*)(wsl + c * 128);   // coalesced L2
            float4 y0 = *(const float4*)(ysw + c * 64);    // warp-uniform LDS
            float4 y1 = *(const float4*)(ysw + c * 64 + 4);
            float yv[8] = {y0.x, y0.y, y0.z, y0.w, y1.x, y1.y, y1.z, y1.w};
#pragma unroll
            for (int pi = 0; pi < 8; pi++) {
                za[pi][0] += yv[pi] * wv.x;
                za[pi][1] += yv[pi] * wv.y;
                za[pi][2] += yv[pi] * wv.z;
                za[pi][3] += yv[pi] * wv.w;
            }
        }

        float4 bb = *(const float4*)(b2 + 4 * l);
        float bq[4] = {bb.x, bb.y, bb.z, bb.w};
        int hh = h0 + w;                      // source row
#pragma unroll
        for (int q = 0; q < 4; q++) {
            int o = 4 * l + q;
            float* rowp = out + (((size_t)(b * OUT_ + o) * (2 * H_)) + 2 * hh) * (2 * W_) + 2 * w0;
#pragma unroll
            for (int pr = 0; pr < 4; pr++) {
                float z0 = za[2 * pr][q] + bq[q];
                float z1 = za[2 * pr + 1][q] + bq[q];
                float4 v = make_float4(z0, z0, z1, z1);
                *(float4*)(rowp + 4 * pr)          = v;   // row 2h
                *(float4*)(rowp + 2 * W_ + 4 * pr) = v;   // row 2h+1
            }
        }
    }
}

// ---------------------------------------------------------------------------
extern "C" void kernel_launch(void* const* d_in, const int* in_sizes, int n_in,
                              void* d_out, int out_size) {
    const float* x  = (const float*)d_in[0];
    const float* w1 = (const float*)d_in[1];
    const float* b1 = (const float*)d_in[2];
    const float* w2 = (const float*)d_in[3];
    const float* b2 = (const float*)d_in[4];
    float* out = (float*)d_out;

    cudaFuncSetAttribute(fused_kernel,
                         cudaFuncAttributeMaxDynamicSharedMemorySize, SM_TOT);

    prep_kernel<<<(LK * C_ * 9 + C_ * 9 * 3 + 255) / 256, 256>>>(w1, w2);
    fused_kernel<<<256, 256, SM_TOT>>>(x, b1, b2, out);
}